// round 10
// baseline (speedup 1.0000x reference)
#include <cuda_runtime.h>
#include <math.h>

#define NQ 24
#define BATCH 4
#define DIMQ (1 << NQ)          // 2^24 rows
#define HALF (1 << (NQ - 1))    // 2^23 pair count
#define TPB 256

// 256-bit memory-op variant (sm_100+ LDG.E.256 / STG.E.256).
// Each thread handles 2 consecutive pair rows (2i, 2i+1): one v8.f32 load
// per stream covers both rows (32 bytes, 32B-aligned). Per warp each load
// instruction moves 1KB contiguous -> better DRAM burst locality, half the
// LSU/L1tex queue entries of the float4 version.
struct __align__(32) f32x8 { float v[8]; };

__device__ __forceinline__ void ldg256(f32x8& d, const float* p) {
    asm volatile("ld.global.cs.v8.f32 {%0,%1,%2,%3,%4,%5,%6,%7}, [%8];"
                 : "=f"(d.v[0]), "=f"(d.v[1]), "=f"(d.v[2]), "=f"(d.v[3]),
                   "=f"(d.v[4]), "=f"(d.v[5]), "=f"(d.v[6]), "=f"(d.v[7])
                 : "l"(p));
}
__device__ __forceinline__ void stg256(float* p, const f32x8& d) {
    asm volatile("st.global.cs.v8.f32 [%0], {%1,%2,%3,%4,%5,%6,%7,%8};"
                 :: "l"(p),
                    "f"(d.v[0]), "f"(d.v[1]), "f"(d.v[2]), "f"(d.v[3]),
                    "f"(d.v[4]), "f"(d.v[5]), "f"(d.v[6]), "f"(d.v[7])
                 : "memory");
}

__global__ __launch_bounds__(TPB) void u_gate_kernel(
    const float* __restrict__ sr,    // state_real (DIM, 4) flat
    const float* __restrict__ si,    // state_imag (DIM, 4) flat
    const float* __restrict__ thetas,// (3,4): phi[4], theta[4], omega[4]
    float* __restrict__ outr,        // out real plane (DIM, 4) flat
    float* __restrict__ outi)        // out imag plane (DIM, 4) flat
{
    // u[b][0..7] = {u00r,u00i, u01r,u01i, u10r,u10i, u11r,u11i}
    __shared__ float u[BATCH * 8];

    const int tid = threadIdx.x;
    if (tid < BATCH) {
        float phi   = thetas[0 * BATCH + tid];
        float theta = thetas[1 * BATCH + tid];
        float omega = thetas[2 * BATCH + tid];
        float a = 0.5f * (phi + omega);
        float b = 0.5f * (phi - omega);
        float sa, ca, sb, cb, st, ct;
        sincosf(a, &sa, &ca);
        sincosf(b, &sb, &cb);
        sincosf(0.5f * theta, &st, &ct);
        // u00 = ct*(ca - i sa); u01 = -st*(cb + i sb)
        // u10 = st*(cb - i sb); u11 = ct*(ca + i sa)
        float* ub = &u[tid * 8];
        ub[0] =  ct * ca;  ub[1] = -ct * sa;
        ub[2] = -st * cb;  ub[3] = -st * sb;
        ub[4] =  st * cb;  ub[5] = -st * sb;
        ub[6] =  ct * ca;  ub[7] =  ct * sa;
    }
    __syncthreads();

    // Thread handles rows r0 = 2*g, r0+1 (both in lower half) and their
    // partners r0+HALF, r0+1+HALF.
    const unsigned g  = blockIdx.x * TPB + tid;     // < 2^22
    const unsigned r0 = 2u * g;                      // even row, 32B aligned
    const unsigned e0 = r0 * BATCH;                  // float offset lower half
    const unsigned e1 = (r0 + HALF) * BATCH;         // float offset upper half

    f32x8 s0r, s0i, s1r, s1i;
    ldg256(s0r, sr + e0);
    ldg256(s0i, si + e0);
    ldg256(s1r, sr + e1);
    ldg256(s1i, si + e1);

    f32x8 o0r, o0i, o1r, o1i;

#pragma unroll
    for (int k = 0; k < 8; k++) {          // k = row_in_pair*4 + b
        const int b = k & 3;
        float u00r = u[b*8+0], u00i = u[b*8+1];
        float u01r = u[b*8+2], u01i = u[b*8+3];
        float u10r = u[b*8+4], u10i = u[b*8+5];
        float u11r = u[b*8+6], u11i = u[b*8+7];
        float x0r = s0r.v[k], x0i = s0i.v[k];
        float x1r = s1r.v[k], x1i = s1i.v[k];

        o0r.v[k] = u00r*x0r - u00i*x0i + u01r*x1r - u01i*x1i;
        o0i.v[k] = u00r*x0i + u00i*x0r + u01r*x1i + u01i*x1r;
        o1r.v[k] = u10r*x0r - u10i*x0i + u11r*x1r - u11i*x1i;
        o1i.v[k] = u10r*x0i + u10i*x0r + u11r*x1i + u11i*x1r;
    }

    stg256(outr + e0, o0r);
    stg256(outi + e0, o0i);
    stg256(outr + e1, o1r);
    stg256(outi + e1, o1i);
}

extern "C" void kernel_launch(void* const* d_in, const int* in_sizes, int n_in,
                              void* d_out, int out_size)
{
    const float* sr = (const float*)d_in[0];   // state_real (DIM, 4)
    const float* si = (const float*)d_in[1];   // state_imag (DIM, 4)
    const float* th = (const float*)d_in[2];   // thetas (3, 4)

    float* outr = (float*)d_out;               // real plane
    float* outi = outr + (size_t)DIMQ * BATCH; // imag plane

    dim3 grid(HALF / (2 * TPB));  // 16384 blocks of 256, 2 rows/thread
    u_gate_kernel<<<grid, TPB>>>(sr, si, th, outr, outi);
}

// round 11
// speedup vs baseline: 1.0010x; 1.0010x over previous
#include <cuda_runtime.h>
#include <math.h>

#define NQ 24
#define BATCH 4
#define DIMQ (1 << NQ)          // 2^24 rows
#define HALF (1 << (NQ - 1))    // 2^23 pair count
#define TPB 256

// FINAL — batched single-qubit U gate (qubit 0 = most-significant axis) on a
// 2^24-dim complex state, BATCH=4.
//
// One thread per pair index i in [0, 2^23).
// State (DIM, B=4) row-major -> each row is one float4 (all 4 batches).
// Pair partner row: i + 2^23. Output (2, DIM, B): real plane, imag plane.
//
// Roofline analysis: traffic is provably minimal (1.074 GB: every input byte
// read once, every output byte written once; fp32 fixed by contract).
// Measured 6.7-6.8 TB/s = 84-85% of 8 TB/s HBM spec across a 10-round sweep
// of TPB {128,256,512}, pairs/thread {1,2}, access width {128b,256b}, and
// all cache policies — all within a +-1.5% plateau. The LTS cap is
// path-independent (LDG == TMA), so no staging rewrite can exceed this.
// This config (TPB 256, .cs load/store) was the best measured (156.16 us, 2x).
__global__ __launch_bounds__(TPB) void u_gate_kernel(
    const float4* __restrict__ sr,
    const float4* __restrict__ si,
    const float*  __restrict__ thetas,  // (3,4): phi[4], theta[4], omega[4]
    float4* __restrict__ outr,
    float4* __restrict__ outi)
{
    // u[b][0..7] = {u00r,u00i, u01r,u01i, u10r,u10i, u11r,u11i}
    __shared__ float u[BATCH * 8];

    const int tid = threadIdx.x;
    if (tid < BATCH) {
        float phi   = thetas[0 * BATCH + tid];
        float theta = thetas[1 * BATCH + tid];
        float omega = thetas[2 * BATCH + tid];
        float a = 0.5f * (phi + omega);
        float b = 0.5f * (phi - omega);
        float sa, ca, sb, cb, st, ct;
        sincosf(a, &sa, &ca);
        sincosf(b, &sb, &cb);
        sincosf(0.5f * theta, &st, &ct);
        // u00 = ct*(ca - i sa); u01 = -st*(cb + i sb)
        // u10 = st*(cb - i sb); u11 = ct*(ca + i sa)
        float* ub = &u[tid * 8];
        ub[0] =  ct * ca;  ub[1] = -ct * sa;
        ub[2] = -st * cb;  ub[3] = -st * sb;
        ub[4] =  st * cb;  ub[5] = -st * sb;
        ub[6] =  ct * ca;  ub[7] =  ct * sa;
    }
    __syncthreads();

    const unsigned i0 = blockIdx.x * TPB + tid;  // pair index, < 2^23
    const unsigned i1 = i0 + HALF;

    // 4 independent 16B evict-first loads -> MLP 4, perfectly coalesced
    float4 s0r = __ldcs(&sr[i0]);
    float4 s0i = __ldcs(&si[i0]);
    float4 s1r = __ldcs(&sr[i1]);
    float4 s1i = __ldcs(&si[i1]);

    float4 o0r, o0i, o1r, o1i;

    const float* s0rf = (const float*)&s0r;
    const float* s0if = (const float*)&s0i;
    const float* s1rf = (const float*)&s1r;
    const float* s1if = (const float*)&s1i;
    float* o0rf = (float*)&o0r;
    float* o0if = (float*)&o0i;
    float* o1rf = (float*)&o1r;
    float* o1if = (float*)&o1i;

#pragma unroll
    for (int b = 0; b < BATCH; b++) {
        float u00r = u[b*8+0], u00i = u[b*8+1];
        float u01r = u[b*8+2], u01i = u[b*8+3];
        float u10r = u[b*8+4], u10i = u[b*8+5];
        float u11r = u[b*8+6], u11i = u[b*8+7];
        float x0r = s0rf[b], x0i = s0if[b];
        float x1r = s1rf[b], x1i = s1if[b];

        o0rf[b] = u00r*x0r - u00i*x0i + u01r*x1r - u01i*x1i;
        o0if[b] = u00r*x0i + u00i*x0r + u01r*x1i + u01i*x1r;
        o1rf[b] = u10r*x0r - u10i*x0i + u11r*x1r - u11i*x1i;
        o1if[b] = u10r*x0i + u10i*x0r + u11r*x1i + u11i*x1r;
    }

    // Evict-first stores
    __stcs(&outr[i0], o0r);
    __stcs(&outi[i0], o0i);
    __stcs(&outr[i1], o1r);
    __stcs(&outi[i1], o1i);
}

extern "C" void kernel_launch(void* const* d_in, const int* in_sizes, int n_in,
                              void* d_out, int out_size)
{
    const float4* sr = (const float4*)d_in[0];   // state_real (DIM, 4)
    const float4* si = (const float4*)d_in[1];   // state_imag (DIM, 4)
    const float*  th = (const float*)d_in[2];    // thetas (3, 4)

    float4* outr = (float4*)d_out;               // real plane
    float4* outi = outr + DIMQ;                  // imag plane

    dim3 grid(HALF / TPB);  // 32768 blocks of 256
    u_gate_kernel<<<grid, TPB>>>(sr, si, th, outr, outi);
}